// round 3
// baseline (speedup 1.0000x reference)
#include <cuda_runtime.h>
#include <cuda_bf16.h>
#include <cstdint>
#include <cstddef>

typedef unsigned long long u64;

// Problem constants
#define B_  64
#define T_  1024
#define D_  512
#define H_  768
#define G_  3072   // 4H

// ---------------- static device scratch ----------------
__device__ float g_xz[(size_t)2 * T_ * G_ * B_];   // [dir][t][col][b]  (1.61 GB)
__device__ float g_h[2][3][B_][H_];                // [dir][buf][b][k]
__device__ unsigned g_cnt[2];                      // per-direction barrier counters

// ---------------- f32x2 helpers ----------------
__device__ __forceinline__ void fma2(u64 &d, u64 a, u64 b) {
    asm("fma.rn.f32x2 %0, %1, %2, %0;" : "+l"(d) : "l"(a), "l"(b));
}
__device__ __forceinline__ u64 bcast2(float w) {
    u64 u; asm("mov.b64 %0, {%1, %1};" : "=l"(u) : "f"(w)); return u;
}
__device__ __forceinline__ float usum(u64 v) {
    float a, b; asm("mov.b64 {%0, %1}, %2;" : "=f"(a), "=f"(b) : "l"(v)); return a + b;
}
__device__ __forceinline__ float2 u2f2(u64 v) {
    float2 f; asm("mov.b64 {%0, %1}, %2;" : "=f"(f.x), "=f"(f.y) : "l"(v)); return f;
}

// ---------------- sync helpers ----------------
__device__ __forceinline__ unsigned ld_acq(const unsigned* p) {
    unsigned v;
    asm volatile("ld.acquire.gpu.b32 %0, [%1];" : "=r"(v) : "l"(p) : "memory");
    return v;
}
__device__ __forceinline__ void red_rel_add1(unsigned* p) {
    asm volatile("red.release.gpu.add.u32 [%0], %1;" :: "l"(p), "r"(1u) : "memory");
}

// ---------------- activations (accurate fast-math) ----------------
__device__ __forceinline__ float sigf(float x) {
    return __fdividef(1.0f, 1.0f + __expf(-x));
}
__device__ __forceinline__ float tanh_(float x) {
    return 1.0f - __fdividef(2.0f, __expf(2.0f * x) + 1.0f);
}

// =====================================================================
// Kernel 1: projection  g_xz[dir][t][col][b] = sum_d x[b,t,d]*W[d,col] + bias[col]
// grid (24, 1024, 2), 256 threads. FFMA2-pipe-bound tiled GEMM.
// =====================================================================
__global__ void __launch_bounds__(256, 2)
proj_kernel(const float* __restrict__ x,
            const float* __restrict__ Wf, const float* __restrict__ Wb,
            const float* __restrict__ bf, const float* __restrict__ bb)
{
    if (blockIdx.x == 0 && blockIdx.y == 0 && blockIdx.z == 0 && threadIdx.x == 0) {
        g_cnt[0] = 0; g_cnt[1] = 0;   // reset recurrence barrier (stream-ordered before rnn)
    }

    __shared__ float xs[32][66];      // [k][b], pad 66 keeps u64 reads aligned + low conflict
    __shared__ float ws[32][128];     // [k][col]

    const int t    = blockIdx.y;
    const int dir  = blockIdx.z;
    const int col0 = blockIdx.x * 128;
    const float* W    = dir ? Wb : Wf;
    const float* bias = dir ? bb : bf;

    const int tid = threadIdx.x;
    const int tx  = tid & 15;         // 16 batch groups
    const int ty  = tid >> 4;         // 16 col groups
    const int b0  = tx * 4;
    const int c0  = ty * 8;

    u64 acc[8][2];
#pragma unroll
    for (int j = 0; j < 8; ++j) { acc[j][0] = 0ull; acc[j][1] = 0ull; }

    for (int kc = 0; kc < D_; kc += 32) {
        // load x tile [32k][64b] (transpose in smem)
#pragma unroll
        for (int r = 0; r < 2; ++r) {
            int i  = tid + 256 * r;
            int bb_ = i >> 3, kq = i & 7;
            float4 v = *reinterpret_cast<const float4*>(
                &x[((size_t)bb_ * T_ + t) * D_ + kc + kq * 4]);
            xs[kq*4+0][bb_] = v.x; xs[kq*4+1][bb_] = v.y;
            xs[kq*4+2][bb_] = v.z; xs[kq*4+3][bb_] = v.w;
        }
        // load W tile [32k][128col]
#pragma unroll
        for (int r = 0; r < 4; ++r) {
            int i = tid + 256 * r;
            int k = i >> 5, c4 = i & 31;
            *reinterpret_cast<float4*>(&ws[k][c4 * 4]) =
                *reinterpret_cast<const float4*>(&W[(size_t)(kc + k) * G_ + col0 + c4 * 4]);
        }
        __syncthreads();
#pragma unroll 8
        for (int k = 0; k < 32; ++k) {
            u64 xa = *reinterpret_cast<const u64*>(&xs[k][b0]);
            u64 xb = *reinterpret_cast<const u64*>(&xs[k][b0 + 2]);
#pragma unroll
            for (int h = 0; h < 2; ++h) {
                float4 w4 = *reinterpret_cast<const float4*>(&ws[k][c0 + h * 4]);
                u64 w;
                w = bcast2(w4.x); fma2(acc[h*4+0][0], xa, w); fma2(acc[h*4+0][1], xb, w);
                w = bcast2(w4.y); fma2(acc[h*4+1][0], xa, w); fma2(acc[h*4+1][1], xb, w);
                w = bcast2(w4.z); fma2(acc[h*4+2][0], xa, w); fma2(acc[h*4+2][1], xb, w);
                w = bcast2(w4.w); fma2(acc[h*4+3][0], xa, w); fma2(acc[h*4+3][1], xb, w);
            }
        }
        __syncthreads();
    }

    float* outp = g_xz + (((size_t)dir * T_ + t) * G_ + col0 + c0) * B_;
#pragma unroll
    for (int j = 0; j < 8; ++j) {
        float bv = bias[col0 + c0 + j];
        float2 p = u2f2(acc[j][0]);
        float2 q = u2f2(acc[j][1]);
        float4 v = make_float4(p.x + bv, p.y + bv, q.x + bv, q.y + bv);
        *reinterpret_cast<float4*>(&outp[(size_t)j * B_ + b0]) = v;
    }
}

// =====================================================================
// Kernel 2: persistent bidirectional recurrence.
// grid = 128 CTAs (dir = cta>>6), 384 threads = 12 warps, warp = 1 hidden unit.
// smem: U slice [12 units][384 kp][4 gates][2] (147456 B) + h chunks 2x[64][100] (51200 B).
// =====================================================================
#define HS_PITCH 100
#define RNN_SMEM ((12 * 3072 + 2 * 64 * HS_PITCH) * 4)

__device__ __forceinline__ void cp_chunk(uint32_t smem_h_u32, const float* hsrc, int ch, int tid)
{
    uint32_t dbase = smem_h_u32 + (uint32_t)((ch & 1) * 64 * HS_PITCH * 4);
    const float* sbase = hsrc + ch * 96;
#pragma unroll
    for (int q = 0; q < 4; ++q) {
        int j   = tid + 384 * q;        // 1536 x 16B = 24 KB chunk
        int b   = j / 24;
        int seg = j % 24;
        uint32_t daddr = dbase + (uint32_t)((b * HS_PITCH + seg * 4) * 4);
        const float* saddr = sbase + (size_t)b * H_ + seg * 4;
        asm volatile("cp.async.cg.shared.global [%0], [%1], 16;"
                     :: "r"(daddr), "l"(saddr) : "memory");
    }
    asm volatile("cp.async.commit_group;" ::: "memory");
}

__global__ void __launch_bounds__(384)
rnn_kernel(const float* __restrict__ Uf, const float* __restrict__ Ub,
           float* __restrict__ out)
{
    extern __shared__ float sm[];
    float* Usm = sm;                     // [12][3072]: u*3072 + kp*8 + gate*2 + r
    float* hsm = sm + 12 * 3072;         // [2][64][HS_PITCH]

    const int cta = blockIdx.x;
    const int dir = cta >> 6;
    const int u0  = (cta & 63) * 12;
    const int tid = threadIdx.x;
    const int u   = tid >> 5;            // warp id = local unit
    const int l   = tid & 31;
    const float* U = dir ? Ub : Uf;

    // one-time: load & repack this CTA's U columns: {even-k, odd-k} per gate
    for (int i = tid; i < 12 * 3072; i += 384) {
        int uu  = i / 3072;
        int rem = i - uu * 3072;
        int kp  = rem >> 3;
        int g   = (rem >> 1) & 3;
        int r   = rem & 1;
        Usm[i] = U[(size_t)(2 * kp + r) * G_ + g * H_ + u0 + uu];
    }
    __syncthreads();

    const uint32_t hsm_u32 = (uint32_t)__cvta_generic_to_shared(hsm);
    const float* Ubase = Usm + u * 3072;

    float c0s = 0.0f, c1s = 0.0f;        // cell state for b=l, b=l+32

    for (int s = 0; s < T_; ++s) {
        const int tt = dir ? (T_ - 1 - s) : s;

        // prefetch xz for this step (independent of barrier)
        const float* xzp = g_xz + (((size_t)dir * T_ + tt) * G_ + u0 + u) * B_;
        float zi0 = xzp[0 * H_ * B_ + l], zi1 = xzp[0 * H_ * B_ + l + 32];
        float zf0 = xzp[1 * H_ * B_ + l], zf1 = xzp[1 * H_ * B_ + l + 32];
        float zg0 = xzp[2 * H_ * B_ + l], zg1 = xzp[2 * H_ * B_ + l + 32];
        float zo0 = xzp[3 * H_ * B_ + l], zo1 = xzp[3 * H_ * B_ + l + 32];

        if (s > 0) {
            // wait for all 64 CTAs of this direction to finish step s-1
            if (tid == 0) {
                const unsigned target = 64u * (unsigned)s;
                while (ld_acq(&g_cnt[dir]) < target) {}
            }
            __syncthreads();

            const float* hsrc = &g_h[dir][(s + 2) % 3][0][0];
            u64 acc[4][2];
#pragma unroll
            for (int g = 0; g < 4; ++g) { acc[g][0] = 0ull; acc[g][1] = 0ull; }

            cp_chunk(hsm_u32, hsrc, 0, tid);
            for (int ch = 0; ch < 8; ++ch) {
                if (ch + 1 < 8) cp_chunk(hsm_u32, hsrc, ch + 1, tid);
                if (ch == 7) asm volatile("cp.async.wait_group 0;" ::: "memory");
                else         asm volatile("cp.async.wait_group 1;" ::: "memory");
                __syncthreads();

                const float* hb = hsm + (ch & 1) * 64 * HS_PITCH;
                const float* Uc = Ubase + ch * 48 * 8;
#pragma unroll 8
                for (int kp = 0; kp < 48; ++kp) {
                    u64 h0 = *reinterpret_cast<const u64*>(&hb[l * HS_PITCH + kp * 2]);
                    u64 h1 = *reinterpret_cast<const u64*>(&hb[(l + 32) * HS_PITCH + kp * 2]);
                    ulonglong2 uab = *reinterpret_cast<const ulonglong2*>(&Uc[kp * 8]);
                    ulonglong2 ucd = *reinterpret_cast<const ulonglong2*>(&Uc[kp * 8 + 4]);
                    fma2(acc[0][0], h0, uab.x); fma2(acc[0][1], h1, uab.x);
                    fma2(acc[1][0], h0, uab.y); fma2(acc[1][1], h1, uab.y);
                    fma2(acc[2][0], h0, ucd.x); fma2(acc[2][1], h1, ucd.x);
                    fma2(acc[3][0], h0, ucd.y); fma2(acc[3][1], h1, ucd.y);
                }
                __syncthreads();
            }
            zi0 += usum(acc[0][0]); zi1 += usum(acc[0][1]);
            zf0 += usum(acc[1][0]); zf1 += usum(acc[1][1]);
            zg0 += usum(acc[2][0]); zg1 += usum(acc[2][1]);
            zo0 += usum(acc[3][0]); zo1 += usum(acc[3][1]);
        }

        // gates (Keras order i, f, g, o)
        float iv0 = sigf(zi0), fv0 = sigf(zf0), gv0 = tanh_(zg0), ov0 = sigf(zo0);
        float iv1 = sigf(zi1), fv1 = sigf(zf1), gv1 = tanh_(zg1), ov1 = sigf(zo1);
        c0s = fv0 * c0s + iv0 * gv0;
        c1s = fv1 * c1s + iv1 * gv1;
        float h0v = ov0 * tanh_(c0s);
        float h1v = ov1 * tanh_(c1s);

        // publish h for step s
        const int wbuf = s % 3;
        g_h[dir][wbuf][l     ][u0 + u] = h0v;
        g_h[dir][wbuf][l + 32][u0 + u] = h1v;

        // final output [B,T,2H]
        out[((size_t)l        * T_ + tt) * (2 * H_) + dir * H_ + u0 + u] = h0v;
        out[((size_t)(l + 32) * T_ + tt) * (2 * H_) + dir * H_ + u0 + u] = h1v;

        __syncthreads();                 // all h-writes of this CTA done
        if (tid == 0) red_rel_add1(&g_cnt[dir]);
    }
}

// =====================================================================
extern "C" void kernel_launch(void* const* d_in, const int* in_sizes, int n_in,
                              void* d_out, int out_size)
{
    const float* x  = (const float*)d_in[0];
    const float* Wf = (const float*)d_in[1];
    const float* Uf = (const float*)d_in[2];
    const float* bf = (const float*)d_in[3];
    const float* Wb = (const float*)d_in[4];
    const float* Ub = (const float*)d_in[5];
    const float* bb = (const float*)d_in[6];
    float* out = (float*)d_out;

    (void)in_sizes; (void)n_in; (void)out_size;

    cudaFuncSetAttribute(rnn_kernel, cudaFuncAttributeMaxDynamicSharedMemorySize, RNN_SMEM);

    proj_kernel<<<dim3(24, T_, 2), 256>>>(x, Wf, Wb, bf, bb);
    rnn_kernel<<<128, 384, RNN_SMEM>>>(Uf, Ub, out);
}

// round 4
// speedup vs baseline: 1.0059x; 1.0059x over previous
#include <cuda_runtime.h>
#include <cuda_bf16.h>
#include <cstdint>
#include <cstddef>

typedef unsigned long long u64;

// Problem constants
#define B_  64
#define T_  1024
#define D_  512
#define H_  768
#define G_  3072   // 4H

// ---------------- static device scratch ----------------
__device__ float g_xz[(size_t)2 * T_ * G_ * B_];   // [dir][t][col][b]  (1.61 GB)
__device__ float g_h[2][3][B_][H_];                // [dir][buf][b][k]
__device__ unsigned g_cnt[2];                      // per-direction barrier counters

// ---------------- f32x2 helpers ----------------
__device__ __forceinline__ void fma2(u64 &d, u64 a, u64 b) {
    asm("fma.rn.f32x2 %0, %1, %2, %0;" : "+l"(d) : "l"(a), "l"(b));
}
__device__ __forceinline__ u64 bcast2(float w) {
    u64 u; asm("mov.b64 %0, {%1, %1};" : "=l"(u) : "f"(w)); return u;
}
__device__ __forceinline__ float usum(u64 v) {
    float a, b; asm("mov.b64 {%0, %1}, %2;" : "=f"(a), "=f"(b) : "l"(v)); return a + b;
}
__device__ __forceinline__ float2 u2f2(u64 v) {
    float2 f; asm("mov.b64 {%0, %1}, %2;" : "=f"(f.x), "=f"(f.y) : "l"(v)); return f;
}

// ---------------- sync helpers ----------------
__device__ __forceinline__ unsigned ld_acq(const unsigned* p) {
    unsigned v;
    asm volatile("ld.acquire.gpu.b32 %0, [%1];" : "=r"(v) : "l"(p) : "memory");
    return v;
}
__device__ __forceinline__ void red_rel_add1(unsigned* p) {
    asm volatile("red.release.gpu.add.u32 [%0], %1;" :: "l"(p), "r"(1u) : "memory");
}

// ---------------- activations (accurate fast-math) ----------------
__device__ __forceinline__ float sigf(float x) {
    return __fdividef(1.0f, 1.0f + __expf(-x));
}
__device__ __forceinline__ float tanh_(float x) {
    return 1.0f - __fdividef(2.0f, __expf(2.0f * x) + 1.0f);
}

// =====================================================================
// Kernel 1: projection  g_xz[dir][t][col][b] = sum_d x[b,t,d]*W[d,col] + bias[col]
// grid (24, 1024, 2), 256 threads. FFMA2-pipe-bound tiled GEMM.
// =====================================================================
__global__ void __launch_bounds__(256, 2)
proj_kernel(const float* __restrict__ x,
            const float* __restrict__ Wf, const float* __restrict__ Wb,
            const float* __restrict__ bf, const float* __restrict__ bb)
{
    if (blockIdx.x == 0 && blockIdx.y == 0 && blockIdx.z == 0 && threadIdx.x == 0) {
        g_cnt[0] = 0; g_cnt[1] = 0;   // reset recurrence barrier (stream-ordered before rnn)
    }

    __shared__ float xs[32][66];      // [k][b], pad 66 keeps u64 reads aligned + low conflict
    __shared__ float ws[32][128];     // [k][col]

    const int t    = blockIdx.y;
    const int dir  = blockIdx.z;
    const int col0 = blockIdx.x * 128;
    const float* W    = dir ? Wb : Wf;
    const float* bias = dir ? bb : bf;

    const int tid = threadIdx.x;
    const int tx  = tid & 15;         // 16 batch groups
    const int ty  = tid >> 4;         // 16 col groups
    const int b0  = tx * 4;
    const int c0  = ty * 8;

    u64 acc[8][2];
#pragma unroll
    for (int j = 0; j < 8; ++j) { acc[j][0] = 0ull; acc[j][1] = 0ull; }

    for (int kc = 0; kc < D_; kc += 32) {
        // load x tile [32k][64b] (transpose in smem)
#pragma unroll
        for (int r = 0; r < 2; ++r) {
            int i  = tid + 256 * r;
            int bb_ = i >> 3, kq = i & 7;
            float4 v = *reinterpret_cast<const float4*>(
                &x[((size_t)bb_ * T_ + t) * D_ + kc + kq * 4]);
            xs[kq*4+0][bb_] = v.x; xs[kq*4+1][bb_] = v.y;
            xs[kq*4+2][bb_] = v.z; xs[kq*4+3][bb_] = v.w;
        }
        // load W tile [32k][128col]
#pragma unroll
        for (int r = 0; r < 4; ++r) {
            int i = tid + 256 * r;
            int k = i >> 5, c4 = i & 31;
            *reinterpret_cast<float4*>(&ws[k][c4 * 4]) =
                *reinterpret_cast<const float4*>(&W[(size_t)(kc + k) * G_ + col0 + c4 * 4]);
        }
        __syncthreads();
#pragma unroll 8
        for (int k = 0; k < 32; ++k) {
            u64 xa = *reinterpret_cast<const u64*>(&xs[k][b0]);
            u64 xb = *reinterpret_cast<const u64*>(&xs[k][b0 + 2]);
#pragma unroll
            for (int h = 0; h < 2; ++h) {
                float4 w4 = *reinterpret_cast<const float4*>(&ws[k][c0 + h * 4]);
                u64 w;
                w = bcast2(w4.x); fma2(acc[h*4+0][0], xa, w); fma2(acc[h*4+0][1], xb, w);
                w = bcast2(w4.y); fma2(acc[h*4+1][0], xa, w); fma2(acc[h*4+1][1], xb, w);
                w = bcast2(w4.z); fma2(acc[h*4+2][0], xa, w); fma2(acc[h*4+2][1], xb, w);
                w = bcast2(w4.w); fma2(acc[h*4+3][0], xa, w); fma2(acc[h*4+3][1], xb, w);
            }
        }
        __syncthreads();
    }

    float* outp = g_xz + (((size_t)dir * T_ + t) * G_ + col0 + c0) * B_;
#pragma unroll
    for (int j = 0; j < 8; ++j) {
        float bv = bias[col0 + c0 + j];
        float2 p = u2f2(acc[j][0]);
        float2 q = u2f2(acc[j][1]);
        float4 v = make_float4(p.x + bv, p.y + bv, q.x + bv, q.y + bv);
        *reinterpret_cast<float4*>(&outp[(size_t)j * B_ + b0]) = v;
    }
}

// =====================================================================
// Kernel 2: persistent bidirectional recurrence.
// grid = 128 CTAs (dir = cta>>6), 384 threads = 12 warps, warp = 1 hidden unit.
// smem: U slice [12 units][384 kp][4 gates][2] (147456 B) + h chunks 2x[64][100] (51200 B).
// =====================================================================
#define HS_PITCH 100
#define RNN_SMEM ((12 * 3072 + 2 * 64 * HS_PITCH) * 4)

__device__ __forceinline__ void cp_chunk(uint32_t smem_h_u32, const float* hsrc, int ch, int tid)
{
    uint32_t dbase = smem_h_u32 + (uint32_t)((ch & 1) * 64 * HS_PITCH * 4);
    const float* sbase = hsrc + ch * 96;
#pragma unroll
    for (int q = 0; q < 4; ++q) {
        int j   = tid + 384 * q;        // 1536 x 16B = 24 KB chunk
        int b   = j / 24;
        int seg = j % 24;
        uint32_t daddr = dbase + (uint32_t)((b * HS_PITCH + seg * 4) * 4);
        const float* saddr = sbase + (size_t)b * H_ + seg * 4;
        asm volatile("cp.async.cg.shared.global [%0], [%1], 16;"
                     :: "r"(daddr), "l"(saddr) : "memory");
    }
    asm volatile("cp.async.commit_group;" ::: "memory");
}

__global__ void __launch_bounds__(384)
rnn_kernel(const float* __restrict__ Uf, const float* __restrict__ Ub,
           float* __restrict__ out)
{
    extern __shared__ float sm[];
    float* Usm = sm;                     // [12][3072]: u*3072 + kp*8 + gate*2 + r
    float* hsm = sm + 12 * 3072;         // [2][64][HS_PITCH]

    const int cta = blockIdx.x;
    const int dir = cta >> 6;
    const int u0  = (cta & 63) * 12;
    const int tid = threadIdx.x;
    const int u   = tid >> 5;            // warp id = local unit
    const int l   = tid & 31;
    const float* U = dir ? Ub : Uf;

    // one-time: load & repack this CTA's U columns: {even-k, odd-k} per gate
    for (int i = tid; i < 12 * 3072; i += 384) {
        int uu  = i / 3072;
        int rem = i - uu * 3072;
        int kp  = rem >> 3;
        int g   = (rem >> 1) & 3;
        int r   = rem & 1;
        Usm[i] = U[(size_t)(2 * kp + r) * G_ + g * H_ + u0 + uu];
    }
    __syncthreads();

    const uint32_t hsm_u32 = (uint32_t)__cvta_generic_to_shared(hsm);
    const float* Ubase = Usm + u * 3072;

    float c0s = 0.0f, c1s = 0.0f;        // cell state for b=l, b=l+32

    for (int s = 0; s < T_; ++s) {
        const int tt = dir ? (T_ - 1 - s) : s;

        // prefetch xz for this step (independent of barrier)
        const float* xzp = g_xz + (((size_t)dir * T_ + tt) * G_ + u0 + u) * B_;
        float zi0 = xzp[0 * H_ * B_ + l], zi1 = xzp[0 * H_ * B_ + l + 32];
        float zf0 = xzp[1 * H_ * B_ + l], zf1 = xzp[1 * H_ * B_ + l + 32];
        float zg0 = xzp[2 * H_ * B_ + l], zg1 = xzp[2 * H_ * B_ + l + 32];
        float zo0 = xzp[3 * H_ * B_ + l], zo1 = xzp[3 * H_ * B_ + l + 32];

        if (s > 0) {
            // wait for all 64 CTAs of this direction to finish step s-1
            if (tid == 0) {
                const unsigned target = 64u * (unsigned)s;
                while (ld_acq(&g_cnt[dir]) < target) {}
            }
            __syncthreads();

            const float* hsrc = &g_h[dir][(s + 2) % 3][0][0];
            u64 acc[4][2];
#pragma unroll
            for (int g = 0; g < 4; ++g) { acc[g][0] = 0ull; acc[g][1] = 0ull; }

            cp_chunk(hsm_u32, hsrc, 0, tid);
            for (int ch = 0; ch < 8; ++ch) {
                if (ch + 1 < 8) cp_chunk(hsm_u32, hsrc, ch + 1, tid);
                if (ch == 7) asm volatile("cp.async.wait_group 0;" ::: "memory");
                else         asm volatile("cp.async.wait_group 1;" ::: "memory");
                __syncthreads();

                const float* hb = hsm + (ch & 1) * 64 * HS_PITCH;
                const float* Uc = Ubase + ch * 48 * 8;
#pragma unroll 8
                for (int kp = 0; kp < 48; ++kp) {
                    u64 h0 = *reinterpret_cast<const u64*>(&hb[l * HS_PITCH + kp * 2]);
                    u64 h1 = *reinterpret_cast<const u64*>(&hb[(l + 32) * HS_PITCH + kp * 2]);
                    ulonglong2 uab = *reinterpret_cast<const ulonglong2*>(&Uc[kp * 8]);
                    ulonglong2 ucd = *reinterpret_cast<const ulonglong2*>(&Uc[kp * 8 + 4]);
                    fma2(acc[0][0], h0, uab.x); fma2(acc[0][1], h1, uab.x);
                    fma2(acc[1][0], h0, uab.y); fma2(acc[1][1], h1, uab.y);
                    fma2(acc[2][0], h0, ucd.x); fma2(acc[2][1], h1, ucd.x);
                    fma2(acc[3][0], h0, ucd.y); fma2(acc[3][1], h1, ucd.y);
                }
                __syncthreads();
            }
            zi0 += usum(acc[0][0]); zi1 += usum(acc[0][1]);
            zf0 += usum(acc[1][0]); zf1 += usum(acc[1][1]);
            zg0 += usum(acc[2][0]); zg1 += usum(acc[2][1]);
            zo0 += usum(acc[3][0]); zo1 += usum(acc[3][1]);
        }

        // gates (Keras order i, f, g, o)
        float iv0 = sigf(zi0), fv0 = sigf(zf0), gv0 = tanh_(zg0), ov0 = sigf(zo0);
        float iv1 = sigf(zi1), fv1 = sigf(zf1), gv1 = tanh_(zg1), ov1 = sigf(zo1);
        c0s = fv0 * c0s + iv0 * gv0;
        c1s = fv1 * c1s + iv1 * gv1;
        float h0v = ov0 * tanh_(c0s);
        float h1v = ov1 * tanh_(c1s);

        // publish h for step s
        const int wbuf = s % 3;
        g_h[dir][wbuf][l     ][u0 + u] = h0v;
        g_h[dir][wbuf][l + 32][u0 + u] = h1v;

        // final output [B,T,2H]
        out[((size_t)l        * T_ + tt) * (2 * H_) + dir * H_ + u0 + u] = h0v;
        out[((size_t)(l + 32) * T_ + tt) * (2 * H_) + dir * H_ + u0 + u] = h1v;

        __syncthreads();                 // all h-writes of this CTA done
        if (tid == 0) red_rel_add1(&g_cnt[dir]);
    }
}

// =====================================================================
extern "C" void kernel_launch(void* const* d_in, const int* in_sizes, int n_in,
                              void* d_out, int out_size)
{
    const float* x  = (const float*)d_in[0];
    const float* Wf = (const float*)d_in[1];
    const float* Uf = (const float*)d_in[2];
    const float* bf = (const float*)d_in[3];
    const float* Wb = (const float*)d_in[4];
    const float* Ub = (const float*)d_in[5];
    const float* bb = (const float*)d_in[6];
    float* out = (float*)d_out;

    (void)in_sizes; (void)n_in; (void)out_size;

    cudaFuncSetAttribute(rnn_kernel, cudaFuncAttributeMaxDynamicSharedMemorySize, RNN_SMEM);

    proj_kernel<<<dim3(24, T_, 2), 256>>>(x, Wf, Wb, bf, bb);
    rnn_kernel<<<128, 384, RNN_SMEM>>>(Uf, Ub, out);
}

// round 7
// speedup vs baseline: 1.5214x; 1.5125x over previous
#include <cuda_runtime.h>
#include <cuda_bf16.h>
#include <cstdint>
#include <cstddef>

typedef unsigned long long u64;
typedef unsigned int u32;

#define B_  64
#define T_  1024
#define D_  512
#define H_  768
#define G_  3072

// ---------------- static device scratch ----------------
__device__ float g_xz[(size_t)2 * T_ * G_ * B_];                 // [dir][t][col][b]
__device__ __align__(16) __nv_bfloat16 g_hbf[2][3][2][B_][H_];   // [dir][buf][hi/lo][b][k]
__device__ unsigned g_cnt[2];

// ---------------- helpers ----------------
__device__ __forceinline__ void fma2(u64 &d, u64 a, u64 b) {
    asm("fma.rn.f32x2 %0, %1, %2, %0;" : "+l"(d) : "l"(a), "l"(b));
}
__device__ __forceinline__ u64 bcast2(float w) {
    u64 u; asm("mov.b64 %0, {%1, %1};" : "=l"(u) : "f"(w)); return u;
}
__device__ __forceinline__ float2 u2f2(u64 v) {
    float2 f; asm("mov.b64 {%0, %1}, %2;" : "=f"(f.x), "=f"(f.y) : "l"(v)); return f;
}
__device__ __forceinline__ unsigned ld_acq(const unsigned* p) {
    unsigned v; asm volatile("ld.acquire.gpu.b32 %0, [%1];" : "=r"(v) : "l"(p) : "memory"); return v;
}
__device__ __forceinline__ void red_rel_add1(unsigned* p) {
    asm volatile("red.release.gpu.add.u32 [%0], %1;" :: "l"(p), "r"(1u) : "memory");
}
__device__ __forceinline__ float sigf(float x) { return __fdividef(1.0f, 1.0f + __expf(-x)); }
__device__ __forceinline__ float tanh_(float x) { return 1.0f - __fdividef(2.0f, __expf(2.0f*x) + 1.0f); }
__device__ __forceinline__ u32 smem_u32(const void* p) {
    u32 a; asm("{ .reg .u64 t; cvta.to.shared.u64 t, %1; cvt.u32.u64 %0, t; }" : "=r"(a) : "l"(p)); return a;
}

#define LDSM4(r, a) \
    asm volatile("ldmatrix.sync.aligned.m8n8.x4.shared.b16 {%0,%1,%2,%3}, [%4];" \
        : "=r"((r)[0]),"=r"((r)[1]),"=r"((r)[2]),"=r"((r)[3]) : "r"(a))
#define LDSM4T(r, a) \
    asm volatile("ldmatrix.sync.aligned.m8n8.x4.trans.shared.b16 {%0,%1,%2,%3}, [%4];" \
        : "=r"((r)[0]),"=r"((r)[1]),"=r"((r)[2]),"=r"((r)[3]) : "r"(a))
#define MMA(d, a, b0, b1) \
    asm volatile("mma.sync.aligned.m16n8k16.row.col.f32.bf16.bf16.f32 " \
        "{%0,%1,%2,%3}, {%4,%5,%6,%7}, {%8,%9}, {%0,%1,%2,%3};" \
        : "+f"((d)[0]),"+f"((d)[1]),"+f"((d)[2]),"+f"((d)[3]) \
        : "r"((a)[0]),"r"((a)[1]),"r"((a)[2]),"r"((a)[3]), "r"(b0),"r"(b1))

// =====================================================================
// Kernel 1: projection (known-good FFMA2 GEMM)
// =====================================================================
__global__ void __launch_bounds__(256, 2)
proj_kernel(const float* __restrict__ x,
            const float* __restrict__ Wf, const float* __restrict__ Wb,
            const float* __restrict__ bf, const float* __restrict__ bb)
{
    if (blockIdx.x == 0 && blockIdx.y == 0 && blockIdx.z == 0 && threadIdx.x == 0) {
        g_cnt[0] = 0; g_cnt[1] = 0;
    }
    __shared__ float xs[32][66];
    __shared__ float ws[32][128];

    const int t = blockIdx.y, dir = blockIdx.z, col0 = blockIdx.x * 128;
    const float* W    = dir ? Wb : Wf;
    const float* bias = dir ? bb : bf;
    const int tid = threadIdx.x;
    const int b0 = (tid & 15) * 4, c0 = (tid >> 4) * 8;

    u64 acc[8][2];
#pragma unroll
    for (int j = 0; j < 8; ++j) { acc[j][0] = 0ull; acc[j][1] = 0ull; }

    for (int kc = 0; kc < D_; kc += 32) {
#pragma unroll
        for (int r = 0; r < 2; ++r) {
            int i = tid + 256 * r;
            int bb_ = i >> 3, kq = i & 7;
            float4 v = *reinterpret_cast<const float4*>(&x[((size_t)bb_ * T_ + t) * D_ + kc + kq * 4]);
            xs[kq*4+0][bb_] = v.x; xs[kq*4+1][bb_] = v.y;
            xs[kq*4+2][bb_] = v.z; xs[kq*4+3][bb_] = v.w;
        }
#pragma unroll
        for (int r = 0; r < 4; ++r) {
            int i = tid + 256 * r;
            int k = i >> 5, c4 = i & 31;
            *reinterpret_cast<float4*>(&ws[k][c4 * 4]) =
                *reinterpret_cast<const float4*>(&W[(size_t)(kc + k) * G_ + col0 + c4 * 4]);
        }
        __syncthreads();
#pragma unroll 8
        for (int k = 0; k < 32; ++k) {
            u64 xa = *reinterpret_cast<const u64*>(&xs[k][b0]);
            u64 xb = *reinterpret_cast<const u64*>(&xs[k][b0 + 2]);
#pragma unroll
            for (int h = 0; h < 2; ++h) {
                float4 w4 = *reinterpret_cast<const float4*>(&ws[k][c0 + h * 4]);
                u64 w;
                w = bcast2(w4.x); fma2(acc[h*4+0][0], xa, w); fma2(acc[h*4+0][1], xb, w);
                w = bcast2(w4.y); fma2(acc[h*4+1][0], xa, w); fma2(acc[h*4+1][1], xb, w);
                w = bcast2(w4.z); fma2(acc[h*4+2][0], xa, w); fma2(acc[h*4+2][1], xb, w);
                w = bcast2(w4.w); fma2(acc[h*4+3][0], xa, w); fma2(acc[h*4+3][1], xb, w);
            }
        }
        __syncthreads();
    }
    float* outp = g_xz + (((size_t)dir * T_ + t) * G_ + col0 + c0) * B_;
#pragma unroll
    for (int j = 0; j < 8; ++j) {
        float bv = bias[col0 + c0 + j];
        float2 p = u2f2(acc[j][0]);
        float2 q = u2f2(acc[j][1]);
        *reinterpret_cast<float4*>(&outp[(size_t)j * B_ + b0]) =
            make_float4(p.x + bv, p.y + bv, q.x + bv, q.y + bv);
    }
}

// =====================================================================
// Kernel 2: persistent recurrence on mma.sync bf16 hi/lo.
// 128 CTAs (64/dir), 128 threads. smem: U[768][104] bf16 (156KB) + 2 A bufs
// [128][136] bf16 (68KB); z exchange aliases A buf 0.
// =====================================================================
#define BPITCH 208              // U row bytes (104 bf16)
#define APITCH 272              // A row bytes (136 bf16)
#define HA0_   159744
#define HA1_   194560
#define RNN_SMEM 229376

__device__ __forceinline__ void cp_chunk(u32 dst, const __nv_bfloat16* hsrc, int ch, int tid)
{
#pragma unroll
    for (int q = 0; q < 16; ++q) {
        int j = q * 128 + tid;
        int r = j >> 4, seg = j & 15;
        u32 d = dst + (u32)(r * APITCH + seg * 16);
        const void* src = hsrc + (size_t)r * H_ + ch * 128 + seg * 8;
        asm volatile("cp.async.cg.shared.global [%0], [%1], 16;" :: "r"(d), "l"(src) : "memory");
    }
    asm volatile("cp.async.commit_group;" ::: "memory");
}

__global__ void __launch_bounds__(128)
rnn_kernel(const float* __restrict__ Uf, const float* __restrict__ Ub, float* __restrict__ out)
{
    extern __shared__ char smem[];
    const u32 sb = smem_u32(smem);
    const int tid = threadIdx.x, w = tid >> 5, l = tid & 31;
    const int dir = blockIdx.x >> 6;
    const int u0  = (blockIdx.x & 63) * 12;
    const float* U = dir ? Ub : Uf;

    // one-time U fill: Bsm[k][n'], n' = gate*12+unit (hi), +48 (lo)
    for (int i = tid; i < 768 * 96; i += 128) {
        int k = i / 96, n = i - k * 96;
        int nn = (n < 48) ? n : n - 48;          // FIXED: was n & 47 (47 is not a mask!)
        int g = nn / 12, uu = nn - g * 12;
        float v = U[(size_t)k * G_ + g * H_ + u0 + uu];
        __nv_bfloat16 hi = __float2bfloat16(v);
        __nv_bfloat16 val = (n < 48) ? hi : __float2bfloat16(v - __bfloat162float(hi));
        *reinterpret_cast<__nv_bfloat16*>(smem + k * BPITCH + n * 2) = val;
    }
    __syncthreads();

    float* zsm = reinterpret_cast<float*>(smem + HA0_);   // [2][64][50], aliases A buf0
    const int b = tid & 63, uh = tid >> 6;
    float cst[6] = {0, 0, 0, 0, 0, 0};

    // per-lane ldmatrix address components
    const u32 aoff = (u32)((32 * w + (l & 15)) * APITCH + (l >> 4) * 16);
    const u32 boff = (u32)(((l & 7) + 8 * ((l >> 3) & 1)) * BPITCH + (l >> 4) * 16);
    const int qd = w >> 1;

    for (int s = 0; s < T_; ++s) {
        const int tt = dir ? (T_ - 1 - s) : s;

        if (s > 0) {
            if (tid == 0) { while (ld_acq(&g_cnt[dir]) < 64u * (u32)s) {} }
            __syncthreads();
        }

        // xz loads (long latency, overlap with MMA pipeline)
        float xzv[24];
        const float* xzb = g_xz + (((size_t)dir * T_ + tt) * G_ + u0) * B_ + b;
#pragma unroll
        for (int g4 = 0; g4 < 4; ++g4)
#pragma unroll
            for (int j = 0; j < 6; ++j)
                xzv[g4 * 6 + j] = xzb[(size_t)(g4 * H_ + uh * 6 + j) * B_];

        if (s > 0) {
            const __nv_bfloat16* hsrc = &g_hbf[dir][(s + 2) % 3][0][0][0];
            float acc[2][12][4];
#pragma unroll
            for (int m = 0; m < 2; ++m)
#pragma unroll
                for (int n = 0; n < 12; ++n)
#pragma unroll
                    for (int e = 0; e < 4; ++e) acc[m][n][e] = 0.0f;

            cp_chunk(sb + HA0_, hsrc, 0, tid);
            for (int ch = 0; ch < 6; ++ch) {
                asm volatile("cp.async.wait_group 0;" ::: "memory");
                __syncthreads();
                if (ch + 1 < 6) cp_chunk(sb + ((ch & 1) ? HA0_ : HA1_), hsrc, ch + 1, tid);

                const u32 aA  = sb + ((ch & 1) ? HA1_ : HA0_) + aoff;
                const u32 aB0 = sb + (u32)(ch * 128 * BPITCH) + boff;
#pragma unroll
                for (int ks = 0; ks < 8; ++ks) {
                    u32 a0[4], a1[4];
                    LDSM4(a0, aA + ks * 32);
                    LDSM4(a1, aA + ks * 32 + 16 * APITCH);
                    const u32 aBk = aB0 + ks * 16 * BPITCH;
#pragma unroll
                    for (int jp = 0; jp < 6; ++jp) {
                        u32 bq[4];
                        LDSM4T(bq, aBk + jp * 32);
                        MMA(acc[0][2*jp],   a0, bq[0], bq[1]);
                        MMA(acc[0][2*jp+1], a0, bq[2], bq[3]);
                        MMA(acc[1][2*jp],   a1, bq[0], bq[1]);
                        MMA(acc[1][2*jp+1], a1, bq[2], bq[3]);
                    }
                }
            }
            __syncthreads();   // all chunk-4 reads of A buf0 done before zsm writes

            // fold U_hi/U_lo column halves, store per-quadrant partials
            float* zq = zsm + qd * 3200;
#pragma unroll
            for (int mm = 0; mm < 2; ++mm) {
                const int r0 = (w & 1) * 32 + mm * 16 + (l >> 2);
#pragma unroll
                for (int j = 0; j < 6; ++j) {
                    float z0 = acc[mm][j][0] + acc[mm][j+6][0];
                    float z1 = acc[mm][j][1] + acc[mm][j+6][1];
                    float z2 = acc[mm][j][2] + acc[mm][j+6][2];
                    float z3 = acc[mm][j][3] + acc[mm][j+6][3];
                    const int c = 8 * j + 2 * (l & 3);
                    *reinterpret_cast<float2*>(&zq[r0 * 50 + c])       = make_float2(z0, z1);
                    *reinterpret_cast<float2*>(&zq[(r0 + 8) * 50 + c]) = make_float2(z2, z3);
                }
            }
            __syncthreads();
        }

#pragma unroll
        for (int j = 0; j < 6; ++j) {
            const int u = uh * 6 + j;
            float zi = xzv[j], zf = xzv[6 + j], zg = xzv[12 + j], zo = xzv[18 + j];
            if (s > 0) {
                zi += zsm[b * 50 + u]      + zsm[3200 + b * 50 + u];
                zf += zsm[b * 50 + 12 + u] + zsm[3200 + b * 50 + 12 + u];
                zg += zsm[b * 50 + 24 + u] + zsm[3200 + b * 50 + 24 + u];
                zo += zsm[b * 50 + 36 + u] + zsm[3200 + b * 50 + 36 + u];
            }
            float iv = sigf(zi), fv = sigf(zf), gv = tanh_(zg), ov = sigf(zo);
            cst[j] = fv * cst[j] + iv * gv;
            float hv = ov * tanh_(cst[j]);
            __nv_bfloat16 hi = __float2bfloat16(hv);
            __nv_bfloat16 lo = __float2bfloat16(hv - __bfloat162float(hi));
            g_hbf[dir][s % 3][0][b][u0 + u] = hi;
            g_hbf[dir][s % 3][1][b][u0 + u] = lo;
            out[((size_t)b * T_ + tt) * (2 * H_) + dir * H_ + u0 + u] = hv;
        }
        __syncthreads();
        if (tid == 0) red_rel_add1(&g_cnt[dir]);
    }
}

// =====================================================================
extern "C" void kernel_launch(void* const* d_in, const int* in_sizes, int n_in,
                              void* d_out, int out_size)
{
    const float* x  = (const float*)d_in[0];
    const float* Wf = (const float*)d_in[1];
    const float* Uf = (const float*)d_in[2];
    const float* bf = (const float*)d_in[3];
    const float* Wb = (const float*)d_in[4];
    const float* Ub = (const float*)d_in[5];
    const float* bb = (const float*)d_in[6];
    float* out = (float*)d_out;
    (void)in_sizes; (void)n_in; (void)out_size;

    cudaFuncSetAttribute(rnn_kernel, cudaFuncAttributeMaxDynamicSharedMemorySize, RNN_SMEM);

    proj_kernel<<<dim3(24, T_, 2), 256>>>(x, Wf, Wb, bf, bb);
    rnn_kernel<<<128, 128, RNN_SMEM>>>(Uf, Ub, out);
}

// round 8
// speedup vs baseline: 2.0291x; 1.3337x over previous
#include <cuda_runtime.h>
#include <cuda_bf16.h>
#include <cstdint>
#include <cstddef>

typedef unsigned long long u64;
typedef unsigned int u32;
typedef unsigned short u16;

#define B_  64
#define T_  1024
#define D_  512
#define H_  768
#define G_  3072

// ---------------- static device scratch ----------------
__device__ float g_xz[(size_t)2 * T_ * G_ * B_];                 // [dir][t][col][b]
__device__ __align__(16) __nv_bfloat16 g_hbf[2][3][2][B_][H_];   // [dir][buf][hi/lo][b][k]
__device__ __align__(16) __nv_bfloat16 g_xs[(size_t)B_ * T_ * 1536];      // [m=t*64+b][xhi|xlo|xhi]
__device__ __align__(16) __nv_bfloat16 g_ws[(size_t)2 * 1536 * G_];       // [dir][Whi;Whi;Wlo][col]
__device__ unsigned g_cnt[2];

// ---------------- helpers ----------------
__device__ __forceinline__ unsigned ld_acq(const unsigned* p) {
    unsigned v; asm volatile("ld.acquire.gpu.b32 %0, [%1];" : "=r"(v) : "l"(p) : "memory"); return v;
}
__device__ __forceinline__ void red_rel_add1(unsigned* p) {
    asm volatile("red.release.gpu.add.u32 [%0], %1;" :: "l"(p), "r"(1u) : "memory");
}
__device__ __forceinline__ float sigf(float x) { return __fdividef(1.0f, 1.0f + __expf(-x)); }
__device__ __forceinline__ float tanh_(float x) { return 1.0f - __fdividef(2.0f, __expf(2.0f*x) + 1.0f); }
__device__ __forceinline__ u32 smem_u32(const void* p) {
    u32 a; asm("{ .reg .u64 t; cvta.to.shared.u64 t, %1; cvt.u32.u64 %0, t; }" : "=r"(a) : "l"(p)); return a;
}

#define LDSM4(r, a) \
    asm volatile("ldmatrix.sync.aligned.m8n8.x4.shared.b16 {%0,%1,%2,%3}, [%4];" \
        : "=r"((r)[0]),"=r"((r)[1]),"=r"((r)[2]),"=r"((r)[3]) : "r"(a))
#define LDSM4T(r, a) \
    asm volatile("ldmatrix.sync.aligned.m8n8.x4.trans.shared.b16 {%0,%1,%2,%3}, [%4];" \
        : "=r"((r)[0]),"=r"((r)[1]),"=r"((r)[2]),"=r"((r)[3]) : "r"(a))
#define MMA(d, a, b0, b1) \
    asm volatile("mma.sync.aligned.m16n8k16.row.col.f32.bf16.bf16.f32 " \
        "{%0,%1,%2,%3}, {%4,%5,%6,%7}, {%8,%9}, {%0,%1,%2,%3};" \
        : "+f"((d)[0]),"+f"((d)[1]),"+f"((d)[2]),"+f"((d)[3]) \
        : "r"((a)[0]),"r"((a)[1]),"r"((a)[2]),"r"((a)[3]), "r"(b0),"r"(b1))

__device__ __forceinline__ u32 pack2(__nv_bfloat16 a, __nv_bfloat16 b) {
    return (u32)__bfloat16_as_ushort(a) | ((u32)__bfloat16_as_ushort(b) << 16);
}

// =====================================================================
// pack_x: x[b][t][k] fp32 -> g_xs[m=t*64+b][ xhi(512) | xlo(512) | xhi(512) ] bf16
// =====================================================================
__global__ void __launch_bounds__(256) pack_x(const float* __restrict__ x)
{
    if (blockIdx.x == 0 && threadIdx.x == 0) { g_cnt[0] = 0; g_cnt[1] = 0; }
    size_t i4 = (size_t)blockIdx.x * 256 + threadIdx.x;   // 8388608 total
    size_t e  = i4 * 4;
    int b = (int)(e >> 19), t = (int)((e >> 9) & 1023), k = (int)(e & 511);
    float4 v = *reinterpret_cast<const float4*>(x + e);
    __nv_bfloat16 h0 = __float2bfloat16(v.x), h1 = __float2bfloat16(v.y);
    __nv_bfloat16 h2 = __float2bfloat16(v.z), h3 = __float2bfloat16(v.w);
    __nv_bfloat16 l0 = __float2bfloat16(v.x - __bfloat162float(h0));
    __nv_bfloat16 l1 = __float2bfloat16(v.y - __bfloat162float(h1));
    __nv_bfloat16 l2 = __float2bfloat16(v.z - __bfloat162float(h2));
    __nv_bfloat16 l3 = __float2bfloat16(v.w - __bfloat162float(h3));
    uint2 hp = make_uint2(pack2(h0, h1), pack2(h2, h3));
    uint2 lp = make_uint2(pack2(l0, l1), pack2(l2, l3));
    size_t m = (size_t)t * 64 + b;
    *reinterpret_cast<uint2*>(&g_xs[m * 1536 + k])        = hp;
    *reinterpret_cast<uint2*>(&g_xs[m * 1536 + 512 + k])  = lp;
    *reinterpret_cast<uint2*>(&g_xs[m * 1536 + 1024 + k]) = hp;
}

// =====================================================================
// pack_w: W[k][col] fp32 -> g_ws[dir][ Whi(512) ; Whi(512) ; Wlo(512) ][col] bf16
// =====================================================================
__global__ void __launch_bounds__(256) pack_w(const float* __restrict__ Wf,
                                              const float* __restrict__ Wb)
{
    size_t idx = (size_t)blockIdx.x * 256 + threadIdx.x;  // 786432 total
    int dir = (int)(idx / 393216);
    size_t r = idx % 393216;
    int k = (int)(r / 768), c4 = (int)(r % 768) * 4;
    const float* W = dir ? Wb : Wf;
    float4 v = *reinterpret_cast<const float4*>(W + (size_t)k * G_ + c4);
    __nv_bfloat16 h0 = __float2bfloat16(v.x), h1 = __float2bfloat16(v.y);
    __nv_bfloat16 h2 = __float2bfloat16(v.z), h3 = __float2bfloat16(v.w);
    __nv_bfloat16 l0 = __float2bfloat16(v.x - __bfloat162float(h0));
    __nv_bfloat16 l1 = __float2bfloat16(v.y - __bfloat162float(h1));
    __nv_bfloat16 l2 = __float2bfloat16(v.z - __bfloat162float(h2));
    __nv_bfloat16 l3 = __float2bfloat16(v.w - __bfloat162float(h3));
    uint2 hp = make_uint2(pack2(h0, h1), pack2(h2, h3));
    uint2 lp = make_uint2(pack2(l0, l1), pack2(l2, l3));
    __nv_bfloat16* base = g_ws + (size_t)dir * 1536 * G_;
    *reinterpret_cast<uint2*>(&base[(size_t)k * G_ + c4])          = hp;
    *reinterpret_cast<uint2*>(&base[(size_t)(k + 512) * G_ + c4])  = hp;
    *reinterpret_cast<uint2*>(&base[(size_t)(k + 1024) * G_ + c4]) = lp;
}

// =====================================================================
// proj_mma: g_xz[dir][t][col][b] = g_xs @ g_ws + bias  (bf16 HMMA, 3-term)
// grid (24 ntile, 512 mtile, 2 dir), 256 threads, 2 CTAs/SM.
// smem: A 2x[128][72bf16] (18432B ea) + B 2x[64][136bf16] (17408B ea) = 71680B
// =====================================================================
#define SA0 0
#define SA1 18432
#define SB0 36864
#define SB1 54272
#define PROJ_SMEM 71680

__device__ __forceinline__ void proj_cp(u32 sa, u32 sbuf, int my, int dir, int bx, int kb, int tid)
{
    const __nv_bfloat16* asrc = g_xs + (size_t)my * 128 * 1536 + kb * 64;
#pragma unroll
    for (int q = 0; q < 4; ++q) {
        int j = q * 256 + tid;                 // 1024: A rows 128 x 8 segs
        int r = j >> 3, seg = j & 7;
        u32 d = sa + (u32)(r * 144 + seg * 16);
        const void* s = asrc + (size_t)r * 1536 + seg * 8;
        asm volatile("cp.async.cg.shared.global [%0], [%1], 16;" :: "r"(d), "l"(s) : "memory");
    }
    const __nv_bfloat16* bsrc = g_ws + ((size_t)dir * 1536 + kb * 64) * G_ + bx * 128;
#pragma unroll
    for (int q = 0; q < 4; ++q) {
        int j = q * 256 + tid;                 // 1024: B rows 64 x 16 segs
        int k = j >> 4, seg = j & 15;
        u32 d = sbuf + (u32)(k * 272 + seg * 16);
        const void* s = bsrc + (size_t)k * G_ + seg * 8;
        asm volatile("cp.async.cg.shared.global [%0], [%1], 16;" :: "r"(d), "l"(s) : "memory");
    }
    asm volatile("cp.async.commit_group;" ::: "memory");
}

__global__ void __launch_bounds__(256, 2)
proj_mma(const float* __restrict__ bf, const float* __restrict__ bb)
{
    extern __shared__ char psm[];
    const u32 sb = smem_u32(psm);
    const int tid = threadIdx.x, w = tid >> 5, l = tid & 31;
    const int bx = blockIdx.x, my = blockIdx.y, dir = blockIdx.z;
    const float* bias = dir ? bb : bf;
    const int mrow0 = 32 * (w & 3), wn = w >> 2;

    const u32 aoff = (u32)((mrow0 + (l & 15)) * 144 + (l >> 4) * 16);
    const u32 boff = (u32)(((l & 7) + 8 * ((l >> 3) & 1)) * 272 + (l >> 4) * 16 + wn * 128);

    float acc[2][8][4];
#pragma unroll
    for (int m = 0; m < 2; ++m)
#pragma unroll
        for (int n = 0; n < 8; ++n)
#pragma unroll
            for (int e = 0; e < 4; ++e) acc[m][n][e] = 0.0f;

    float bv[8][2];
#pragma unroll
    for (int nt = 0; nt < 8; ++nt) {
        int c = bx * 128 + wn * 64 + nt * 8 + 2 * (l & 3);
        bv[nt][0] = bias[c]; bv[nt][1] = bias[c + 1];
    }

    proj_cp(sb + SA0, sb + SB0, my, dir, bx, 0, tid);
    for (int kb = 0; kb < 24; ++kb) {
        asm volatile("cp.async.wait_group 0;" ::: "memory");
        __syncthreads();
        if (kb + 1 < 24)
            proj_cp(sb + (((kb + 1) & 1) ? SA1 : SA0),
                    sb + (((kb + 1) & 1) ? SB1 : SB0), my, dir, bx, kb + 1, tid);
        const u32 uA = sb + ((kb & 1) ? SA1 : SA0) + aoff;
        const u32 uB = sb + ((kb & 1) ? SB1 : SB0) + boff;
#pragma unroll
        for (int ks = 0; ks < 4; ++ks) {
            u32 a0[4], a1[4];
            LDSM4(a0, uA + ks * 32);
            LDSM4(a1, uA + ks * 32 + 16 * 144);
#pragma unroll
            for (int j = 0; j < 4; ++j) {
                u32 bq[4];
                LDSM4T(bq, uB + ks * 16 * 272 + j * 32);
                MMA(acc[0][2*j],   a0, bq[0], bq[1]);
                MMA(acc[0][2*j+1], a0, bq[2], bq[3]);
                MMA(acc[1][2*j],   a1, bq[0], bq[1]);
                MMA(acc[1][2*j+1], a1, bq[2], bq[3]);
            }
        }
    }

    // epilogue: D[m][col] -> g_xz[dir][t][col][b], m = t*64+b
#pragma unroll
    for (int mm = 0; mm < 2; ++mm)
#pragma unroll
        for (int p = 0; p < 2; ++p) {
            int m = (my << 7) + mrow0 + mm * 16 + p * 8 + (l >> 2);
            int t = m >> 6, b = m & 63;
            float* basep = g_xz +
                (((size_t)dir * T_ + t) * G_ + bx * 128 + wn * 64 + 2 * (l & 3)) * 64 + b;
#pragma unroll
            for (int nt = 0; nt < 8; ++nt) {
                basep[(size_t)nt * 512]      = acc[mm][nt][2*p]     + bv[nt][0];
                basep[(size_t)nt * 512 + 64] = acc[mm][nt][2*p + 1] + bv[nt][1];
            }
        }
}

// =====================================================================
// Kernel 2: persistent recurrence on mma.sync bf16 hi/lo (proven R7 core;
// only change: xz prefetch hoisted above the inter-CTA spin barrier).
// =====================================================================
#define BPITCH 208
#define APITCH 272
#define HA0_   159744
#define HA1_   194560
#define RNN_SMEM 229376

__device__ __forceinline__ void cp_chunk(u32 dst, const __nv_bfloat16* hsrc, int ch, int tid)
{
#pragma unroll
    for (int q = 0; q < 16; ++q) {
        int j = q * 128 + tid;
        int r = j >> 4, seg = j & 15;
        u32 d = dst + (u32)(r * APITCH + seg * 16);
        const void* src = hsrc + (size_t)r * H_ + ch * 128 + seg * 8;
        asm volatile("cp.async.cg.shared.global [%0], [%1], 16;" :: "r"(d), "l"(src) : "memory");
    }
    asm volatile("cp.async.commit_group;" ::: "memory");
}

__global__ void __launch_bounds__(128)
rnn_kernel(const float* __restrict__ Uf, const float* __restrict__ Ub, float* __restrict__ out)
{
    extern __shared__ char smem[];
    const u32 sb = smem_u32(smem);
    const int tid = threadIdx.x, w = tid >> 5, l = tid & 31;
    const int dir = blockIdx.x >> 6;
    const int u0  = (blockIdx.x & 63) * 12;
    const float* U = dir ? Ub : Uf;

    for (int i = tid; i < 768 * 96; i += 128) {
        int k = i / 96, n = i - k * 96;
        int nn = (n < 48) ? n : n - 48;
        int g = nn / 12, uu = nn - g * 12;
        float v = U[(size_t)k * G_ + g * H_ + u0 + uu];
        __nv_bfloat16 hi = __float2bfloat16(v);
        __nv_bfloat16 val = (n < 48) ? hi : __float2bfloat16(v - __bfloat162float(hi));
        *reinterpret_cast<__nv_bfloat16*>(smem + k * BPITCH + n * 2) = val;
    }
    __syncthreads();

    float* zsm = reinterpret_cast<float*>(smem + HA0_);
    const int b = tid & 63, uh = tid >> 6;
    float cst[6] = {0, 0, 0, 0, 0, 0};

    const u32 aoff = (u32)((32 * w + (l & 15)) * APITCH + (l >> 4) * 16);
    const u32 boff = (u32)(((l & 7) + 8 * ((l >> 3) & 1)) * BPITCH + (l >> 4) * 16);
    const int qd = w >> 1;

    for (int s = 0; s < T_; ++s) {
        const int tt = dir ? (T_ - 1 - s) : s;

        // xz prefetch FIRST (no cross-CTA dependency; overlaps spin latency)
        float xzv[24];
        const float* xzb = g_xz + (((size_t)dir * T_ + tt) * G_ + u0) * B_ + b;
#pragma unroll
        for (int g4 = 0; g4 < 4; ++g4)
#pragma unroll
            for (int j = 0; j < 6; ++j)
                xzv[g4 * 6 + j] = xzb[(size_t)(g4 * H_ + uh * 6 + j) * B_];

        if (s > 0) {
            if (tid == 0) { while (ld_acq(&g_cnt[dir]) < 64u * (u32)s) {} }
            __syncthreads();

            const __nv_bfloat16* hsrc = &g_hbf[dir][(s + 2) % 3][0][0][0];
            float acc[2][12][4];
#pragma unroll
            for (int m = 0; m < 2; ++m)
#pragma unroll
                for (int n = 0; n < 12; ++n)
#pragma unroll
                    for (int e = 0; e < 4; ++e) acc[m][n][e] = 0.0f;

            cp_chunk(sb + HA0_, hsrc, 0, tid);
            for (int ch = 0; ch < 6; ++ch) {
                asm volatile("cp.async.wait_group 0;" ::: "memory");
                __syncthreads();
                if (ch + 1 < 6) cp_chunk(sb + ((ch & 1) ? HA0_ : HA1_), hsrc, ch + 1, tid);

                const u32 aA  = sb + ((ch & 1) ? HA1_ : HA0_) + aoff;
                const u32 aB0 = sb + (u32)(ch * 128 * BPITCH) + boff;
#pragma unroll
                for (int ks = 0; ks < 8; ++ks) {
                    u32 a0[4], a1[4];
                    LDSM4(a0, aA + ks * 32);
                    LDSM4(a1, aA + ks * 32 + 16 * APITCH);
                    const u32 aBk = aB0 + ks * 16 * BPITCH;
#pragma unroll
                    for (int jp = 0; jp < 6; ++jp) {
                        u32 bq[4];
                        LDSM4T(bq, aBk + jp * 32);
                        MMA(acc[0][2*jp],   a0, bq[0], bq[1]);
                        MMA(acc[0][2*jp+1], a0, bq[2], bq[3]);
                        MMA(acc[1][2*jp],   a1, bq[0], bq[1]);
                        MMA(acc[1][2*jp+1], a1, bq[2], bq[3]);
                    }
                }
            }
            __syncthreads();

            float* zq = zsm + qd * 3200;
#pragma unroll
            for (int mm = 0; mm < 2; ++mm) {
                const int r0 = (w & 1) * 32 + mm * 16 + (l >> 2);
#pragma unroll
                for (int j = 0; j < 6; ++j) {
                    float z0 = acc[mm][j][0] + acc[mm][j+6][0];
                    float z1 = acc[mm][j][1] + acc[mm][j+6][1];
                    float z2 = acc[mm][j][2] + acc[mm][j+6][2];
                    float z3 = acc[mm][j][3] + acc[mm][j+6][3];
                    const int c = 8 * j + 2 * (l & 3);
                    *reinterpret_cast<float2*>(&zq[r0 * 50 + c])       = make_float2(z0, z1);
                    *reinterpret_cast<float2*>(&zq[(r0 + 8) * 50 + c]) = make_float2(z2, z3);
                }
            }
            __syncthreads();
        }

#pragma unroll
        for (int j = 0; j < 6; ++j) {
            const int u = uh * 6 + j;
            float zi = xzv[j], zf = xzv[6 + j], zg = xzv[12 + j], zo = xzv[18 + j];
            if (s > 0) {
                zi += zsm[b * 50 + u]      + zsm[3200 + b * 50 + u];
                zf += zsm[b * 50 + 12 + u] + zsm[3200 + b * 50 + 12 + u];
                zg += zsm[b * 50 + 24 + u] + zsm[3200 + b * 50 + 24 + u];
                zo += zsm[b * 50 + 36 + u] + zsm[3200 + b * 50 + 36 + u];
            }
            float iv = sigf(zi), fv = sigf(zf), gv = tanh_(zg), ov = sigf(zo);
            cst[j] = fv * cst[j] + iv * gv;
            float hv = ov * tanh_(cst[j]);
            __nv_bfloat16 hi = __float2bfloat16(hv);
            __nv_bfloat16 lo = __float2bfloat16(hv - __bfloat162float(hi));
            g_hbf[dir][s % 3][0][b][u0 + u] = hi;
            g_hbf[dir][s % 3][1][b][u0 + u] = lo;
            out[((size_t)b * T_ + tt) * (2 * H_) + dir * H_ + u0 + u] = hv;
        }
        __syncthreads();
        if (tid == 0) red_rel_add1(&g_cnt[dir]);
    }
}

// =====================================================================
extern "C" void kernel_launch(void* const* d_in, const int* in_sizes, int n_in,
                              void* d_out, int out_size)
{
    const float* x  = (const float*)d_in[0];
    const float* Wf = (const float*)d_in[1];
    const float* Uf = (const float*)d_in[2];
    const float* bf = (const float*)d_in[3];
    const float* Wb = (const float*)d_in[4];
    const float* Ub = (const float*)d_in[5];
    const float* bb = (const float*)d_in[6];
    float* out = (float*)d_out;
    (void)in_sizes; (void)n_in; (void)out_size;

    cudaFuncSetAttribute(proj_mma, cudaFuncAttributeMaxDynamicSharedMemorySize, PROJ_SMEM);
    cudaFuncSetAttribute(rnn_kernel, cudaFuncAttributeMaxDynamicSharedMemorySize, RNN_SMEM);

    pack_x<<<32768, 256>>>(x);
    pack_w<<<3072, 256>>>(Wf, Wb);
    proj_mma<<<dim3(24, 512, 2), 256, PROJ_SMEM>>>(bf, bb);
    rnn_kernel<<<128, 128, RNN_SMEM>>>(Uf, Ub, out);
}

// round 9
// speedup vs baseline: 2.0344x; 1.0026x over previous
#include <cuda_runtime.h>
#include <cuda_bf16.h>
#include <cstdint>
#include <cstddef>

typedef unsigned long long u64;
typedef unsigned int u32;
typedef unsigned short u16;

#define B_  64
#define T_  1024
#define D_  512
#define H_  768
#define G_  3072

// ---------------- static device scratch ----------------
__device__ float g_xz[(size_t)2 * T_ * G_ * B_];                 // [dir][t][col][b]
__device__ __align__(16) __nv_bfloat16 g_hbf[2][3][2][B_][H_];   // [dir][buf][hi/lo][b][k]
__device__ __align__(16) __nv_bfloat16 g_xs[(size_t)B_ * T_ * 1536];      // [m=t*64+b][xhi|xlo|xhi]
__device__ __align__(16) __nv_bfloat16 g_ws[(size_t)2 * 1536 * G_];       // [dir][Whi;Whi;Wlo][col]
__device__ unsigned g_cnt[2];

// ---------------- helpers ----------------
__device__ __forceinline__ unsigned ld_acq(const unsigned* p) {
    unsigned v; asm volatile("ld.acquire.gpu.b32 %0, [%1];" : "=r"(v) : "l"(p) : "memory"); return v;
}
__device__ __forceinline__ void red_rel_add1(unsigned* p) {
    asm volatile("red.release.gpu.add.u32 [%0], %1;" :: "l"(p), "r"(1u) : "memory");
}
__device__ __forceinline__ float sigf(float x) { return __fdividef(1.0f, 1.0f + __expf(-x)); }
__device__ __forceinline__ float tanh_(float x) { return 1.0f - __fdividef(2.0f, __expf(2.0f*x) + 1.0f); }
__device__ __forceinline__ u32 smem_u32(const void* p) {
    u32 a; asm("{ .reg .u64 t; cvta.to.shared.u64 t, %1; cvt.u32.u64 %0, t; }" : "=r"(a) : "l"(p)); return a;
}

#define LDSM4(r, a) \
    asm volatile("ldmatrix.sync.aligned.m8n8.x4.shared.b16 {%0,%1,%2,%3}, [%4];" \
        : "=r"((r)[0]),"=r"((r)[1]),"=r"((r)[2]),"=r"((r)[3]) : "r"(a))
#define LDSM4T(r, a) \
    asm volatile("ldmatrix.sync.aligned.m8n8.x4.trans.shared.b16 {%0,%1,%2,%3}, [%4];" \
        : "=r"((r)[0]),"=r"((r)[1]),"=r"((r)[2]),"=r"((r)[3]) : "r"(a))
#define MMA(d, a, b0, b1) \
    asm volatile("mma.sync.aligned.m16n8k16.row.col.f32.bf16.bf16.f32 " \
        "{%0,%1,%2,%3}, {%4,%5,%6,%7}, {%8,%9}, {%0,%1,%2,%3};" \
        : "+f"((d)[0]),"+f"((d)[1]),"+f"((d)[2]),"+f"((d)[3]) \
        : "r"((a)[0]),"r"((a)[1]),"r"((a)[2]),"r"((a)[3]), "r"(b0),"r"(b1))

__device__ __forceinline__ u32 pack2(__nv_bfloat16 a, __nv_bfloat16 b) {
    return (u32)__bfloat16_as_ushort(a) | ((u32)__bfloat16_as_ushort(b) << 16);
}

// =====================================================================
// pack_x: x[b][t][k] fp32 -> g_xs[m=t*64+b][ xhi(512) | xlo(512) | xhi(512) ] bf16
// =====================================================================
__global__ void __launch_bounds__(256) pack_x(const float* __restrict__ x)
{
    if (blockIdx.x == 0 && threadIdx.x == 0) { g_cnt[0] = 0; g_cnt[1] = 0; }
    size_t i4 = (size_t)blockIdx.x * 256 + threadIdx.x;
    size_t e  = i4 * 4;
    int b = (int)(e >> 19), t = (int)((e >> 9) & 1023), k = (int)(e & 511);
    float4 v = *reinterpret_cast<const float4*>(x + e);
    __nv_bfloat16 h0 = __float2bfloat16(v.x), h1 = __float2bfloat16(v.y);
    __nv_bfloat16 h2 = __float2bfloat16(v.z), h3 = __float2bfloat16(v.w);
    __nv_bfloat16 l0 = __float2bfloat16(v.x - __bfloat162float(h0));
    __nv_bfloat16 l1 = __float2bfloat16(v.y - __bfloat162float(h1));
    __nv_bfloat16 l2 = __float2bfloat16(v.z - __bfloat162float(h2));
    __nv_bfloat16 l3 = __float2bfloat16(v.w - __bfloat162float(h3));
    uint2 hp = make_uint2(pack2(h0, h1), pack2(h2, h3));
    uint2 lp = make_uint2(pack2(l0, l1), pack2(l2, l3));
    size_t m = (size_t)t * 64 + b;
    *reinterpret_cast<uint2*>(&g_xs[m * 1536 + k])        = hp;
    *reinterpret_cast<uint2*>(&g_xs[m * 1536 + 512 + k])  = lp;
    *reinterpret_cast<uint2*>(&g_xs[m * 1536 + 1024 + k]) = hp;
}

// =====================================================================
// pack_w: W[k][col] fp32 -> g_ws[dir][ Whi(512) ; Whi(512) ; Wlo(512) ][col] bf16
// =====================================================================
__global__ void __launch_bounds__(256) pack_w(const float* __restrict__ Wf,
                                              const float* __restrict__ Wb)
{
    size_t idx = (size_t)blockIdx.x * 256 + threadIdx.x;
    int dir = (int)(idx / 393216);
    size_t r = idx % 393216;
    int k = (int)(r / 768), c4 = (int)(r % 768) * 4;
    const float* W = dir ? Wb : Wf;
    float4 v = *reinterpret_cast<const float4*>(W + (size_t)k * G_ + c4);
    __nv_bfloat16 h0 = __float2bfloat16(v.x), h1 = __float2bfloat16(v.y);
    __nv_bfloat16 h2 = __float2bfloat16(v.z), h3 = __float2bfloat16(v.w);
    __nv_bfloat16 l0 = __float2bfloat16(v.x - __bfloat162float(h0));
    __nv_bfloat16 l1 = __float2bfloat16(v.y - __bfloat162float(h1));
    __nv_bfloat16 l2 = __float2bfloat16(v.z - __bfloat162float(h2));
    __nv_bfloat16 l3 = __float2bfloat16(v.w - __bfloat162float(h3));
    uint2 hp = make_uint2(pack2(h0, h1), pack2(h2, h3));
    uint2 lp = make_uint2(pack2(l0, l1), pack2(l2, l3));
    __nv_bfloat16* base = g_ws + (size_t)dir * 1536 * G_;
    *reinterpret_cast<uint2*>(&base[(size_t)k * G_ + c4])          = hp;
    *reinterpret_cast<uint2*>(&base[(size_t)(k + 512) * G_ + c4])  = hp;
    *reinterpret_cast<uint2*>(&base[(size_t)(k + 1024) * G_ + c4]) = lp;
}

// =====================================================================
// proj_mma (unchanged, known-good)
// =====================================================================
#define SA0 0
#define SA1 18432
#define SB0 36864
#define SB1 54272
#define PROJ_SMEM 71680

__device__ __forceinline__ void proj_cp(u32 sa, u32 sbuf, int my, int dir, int bx, int kb, int tid)
{
    const __nv_bfloat16* asrc = g_xs + (size_t)my * 128 * 1536 + kb * 64;
#pragma unroll
    for (int q = 0; q < 4; ++q) {
        int j = q * 256 + tid;
        int r = j >> 3, seg = j & 7;
        u32 d = sa + (u32)(r * 144 + seg * 16);
        const void* s = asrc + (size_t)r * 1536 + seg * 8;
        asm volatile("cp.async.cg.shared.global [%0], [%1], 16;" :: "r"(d), "l"(s) : "memory");
    }
    const __nv_bfloat16* bsrc = g_ws + ((size_t)dir * 1536 + kb * 64) * G_ + bx * 128;
#pragma unroll
    for (int q = 0; q < 4; ++q) {
        int j = q * 256 + tid;
        int k = j >> 4, seg = j & 15;
        u32 d = sbuf + (u32)(k * 272 + seg * 16);
        const void* s = bsrc + (size_t)k * G_ + seg * 8;
        asm volatile("cp.async.cg.shared.global [%0], [%1], 16;" :: "r"(d), "l"(s) : "memory");
    }
    asm volatile("cp.async.commit_group;" ::: "memory");
}

__global__ void __launch_bounds__(256, 2)
proj_mma(const float* __restrict__ bf, const float* __restrict__ bb)
{
    extern __shared__ char psm[];
    const u32 sb = smem_u32(psm);
    const int tid = threadIdx.x, w = tid >> 5, l = tid & 31;
    const int bx = blockIdx.x, my = blockIdx.y, dir = blockIdx.z;
    const float* bias = dir ? bb : bf;
    const int mrow0 = 32 * (w & 3), wn = w >> 2;

    const u32 aoff = (u32)((mrow0 + (l & 15)) * 144 + (l >> 4) * 16);
    const u32 boff = (u32)(((l & 7) + 8 * ((l >> 3) & 1)) * 272 + (l >> 4) * 16 + wn * 128);

    float acc[2][8][4];
#pragma unroll
    for (int m = 0; m < 2; ++m)
#pragma unroll
        for (int n = 0; n < 8; ++n)
#pragma unroll
            for (int e = 0; e < 4; ++e) acc[m][n][e] = 0.0f;

    float bv[8][2];
#pragma unroll
    for (int nt = 0; nt < 8; ++nt) {
        int c = bx * 128 + wn * 64 + nt * 8 + 2 * (l & 3);
        bv[nt][0] = bias[c]; bv[nt][1] = bias[c + 1];
    }

    proj_cp(sb + SA0, sb + SB0, my, dir, bx, 0, tid);
    for (int kb = 0; kb < 24; ++kb) {
        asm volatile("cp.async.wait_group 0;" ::: "memory");
        __syncthreads();
        if (kb + 1 < 24)
            proj_cp(sb + (((kb + 1) & 1) ? SA1 : SA0),
                    sb + (((kb + 1) & 1) ? SB1 : SB0), my, dir, bx, kb + 1, tid);
        const u32 uA = sb + ((kb & 1) ? SA1 : SA0) + aoff;
        const u32 uB = sb + ((kb & 1) ? SB1 : SB0) + boff;
#pragma unroll
        for (int ks = 0; ks < 4; ++ks) {
            u32 a0[4], a1[4];
            LDSM4(a0, uA + ks * 32);
            LDSM4(a1, uA + ks * 32 + 16 * 144);
#pragma unroll
            for (int j = 0; j < 4; ++j) {
                u32 bq[4];
                LDSM4T(bq, uB + ks * 16 * 272 + j * 32);
                MMA(acc[0][2*j],   a0, bq[0], bq[1]);
                MMA(acc[0][2*j+1], a0, bq[2], bq[3]);
                MMA(acc[1][2*j],   a1, bq[0], bq[1]);
                MMA(acc[1][2*j+1], a1, bq[2], bq[3]);
            }
        }
    }

#pragma unroll
    for (int mm = 0; mm < 2; ++mm)
#pragma unroll
        for (int p = 0; p < 2; ++p) {
            int m = (my << 7) + mrow0 + mm * 16 + p * 8 + (l >> 2);
            int t = m >> 6, b = m & 63;
            float* basep = g_xz +
                (((size_t)dir * T_ + t) * G_ + bx * 128 + wn * 64 + 2 * (l & 3)) * 64 + b;
#pragma unroll
            for (int nt = 0; nt < 8; ++nt) {
                basep[(size_t)nt * 512]      = acc[mm][nt][2*p]     + bv[nt][0];
                basep[(size_t)nt * 512 + 64] = acc[mm][nt][2*p + 1] + bv[nt][1];
            }
        }
}

// =====================================================================
// Kernel 2: persistent recurrence, now 256 threads / 8 warps (M=16/warp).
// =====================================================================
#define BPITCH 208
#define APITCH 272
#define HA0_   159744
#define HA1_   194560
#define RNN_SMEM 229376

__device__ __forceinline__ void cp_chunk(u32 dst, const __nv_bfloat16* hsrc, int ch, int tid)
{
#pragma unroll
    for (int q = 0; q < 8; ++q) {
        int j = q * 256 + tid;               // 2048 x 16B
        int r = j >> 4, seg = j & 15;
        u32 d = dst + (u32)(r * APITCH + seg * 16);
        const void* src = hsrc + (size_t)r * H_ + ch * 128 + seg * 8;
        asm volatile("cp.async.cg.shared.global [%0], [%1], 16;" :: "r"(d), "l"(src) : "memory");
    }
    asm volatile("cp.async.commit_group;" ::: "memory");
}

__global__ void __launch_bounds__(256)
rnn_kernel(const float* __restrict__ Uf, const float* __restrict__ Ub, float* __restrict__ out)
{
    extern __shared__ char smem[];
    const u32 sb = smem_u32(smem);
    const int tid = threadIdx.x, w = tid >> 5, l = tid & 31;
    const int dir = blockIdx.x >> 6;
    const int u0  = (blockIdx.x & 63) * 12;
    const float* U = dir ? Ub : Uf;

    for (int i = tid; i < 768 * 96; i += 256) {
        int k = i / 96, n = i - k * 96;
        int nn = (n < 48) ? n : n - 48;
        int g = nn / 12, uu = nn - g * 12;
        float v = U[(size_t)k * G_ + g * H_ + u0 + uu];
        __nv_bfloat16 hi = __float2bfloat16(v);
        __nv_bfloat16 val = (n < 48) ? hi : __float2bfloat16(v - __bfloat162float(hi));
        *reinterpret_cast<__nv_bfloat16*>(smem + k * BPITCH + n * 2) = val;
    }
    __syncthreads();

    float* zsm = reinterpret_cast<float*>(smem + HA0_);
    const int b = tid & 63, uh = tid >> 6;   // uh in 0..3, 3 units each
    float cst[3] = {0, 0, 0};

    // warp w owns A rows 16w..16w+15 (warps 0-3: h_hi rows, 4-7: h_lo rows)
    const u32 aoff = (u32)((16 * w + (l & 15)) * APITCH + (l >> 4) * 16);
    const u32 boff = (u32)(((l & 7) + 8 * ((l >> 3) & 1)) * BPITCH + (l >> 4) * 16);
    const int qd = w >> 2;

    for (int s = 0; s < T_; ++s) {
        const int tt = dir ? (T_ - 1 - s) : s;

        // xz prefetch first (no cross-CTA dependency)
        float xzv[12];
        const float* xzb = g_xz + (((size_t)dir * T_ + tt) * G_ + u0) * B_ + b;
#pragma unroll
        for (int g4 = 0; g4 < 4; ++g4)
#pragma unroll
            for (int j = 0; j < 3; ++j)
                xzv[g4 * 3 + j] = xzb[(size_t)(g4 * H_ + uh * 3 + j) * B_];

        if (s > 0) {
            if (tid == 0) { while (ld_acq(&g_cnt[dir]) < 64u * (u32)s) {} }
            __syncthreads();

            const __nv_bfloat16* hsrc = &g_hbf[dir][(s + 2) % 3][0][0][0];
            float acc[12][4];
#pragma unroll
            for (int n = 0; n < 12; ++n)
#pragma unroll
                for (int e = 0; e < 4; ++e) acc[n][e] = 0.0f;

            cp_chunk(sb + HA0_, hsrc, 0, tid);
            for (int ch = 0; ch < 6; ++ch) {
                asm volatile("cp.async.wait_group 0;" ::: "memory");
                __syncthreads();
                if (ch + 1 < 6) cp_chunk(sb + ((ch & 1) ? HA0_ : HA1_), hsrc, ch + 1, tid);

                const u32 aA  = sb + ((ch & 1) ? HA1_ : HA0_) + aoff;
                const u32 aB0 = sb + (u32)(ch * 128 * BPITCH) + boff;
#pragma unroll
                for (int ks = 0; ks < 8; ++ks) {
                    u32 a0[4];
                    LDSM4(a0, aA + ks * 32);
                    const u32 aBk = aB0 + ks * 16 * BPITCH;
#pragma unroll
                    for (int jp = 0; jp < 6; ++jp) {
                        u32 bq[4];
                        LDSM4T(bq, aBk + jp * 32);
                        MMA(acc[2*jp],   a0, bq[0], bq[1]);
                        MMA(acc[2*jp+1], a0, bq[2], bq[3]);
                    }
                }
            }
            __syncthreads();   // buf0 reads done before zsm writes

            // fold U_hi/U_lo halves; quadrant 0 = h_hi rows, 1 = h_lo rows
            float* zq = zsm + qd * 3200;
            const int r0 = (w & 3) * 16 + (l >> 2);
#pragma unroll
            for (int j = 0; j < 6; ++j) {
                float z0 = acc[j][0] + acc[j+6][0];
                float z1 = acc[j][1] + acc[j+6][1];
                float z2 = acc[j][2] + acc[j+6][2];
                float z3 = acc[j][3] + acc[j+6][3];
                const int c = 8 * j + 2 * (l & 3);
                *reinterpret_cast<float2*>(&zq[r0 * 50 + c])       = make_float2(z0, z1);
                *reinterpret_cast<float2*>(&zq[(r0 + 8) * 50 + c]) = make_float2(z2, z3);
            }
            __syncthreads();
        }

#pragma unroll
        for (int j = 0; j < 3; ++j) {
            const int u = uh * 3 + j;
            float zi = xzv[j], zf = xzv[3 + j], zg = xzv[6 + j], zo = xzv[9 + j];
            if (s > 0) {
                zi += zsm[b * 50 + u]      + zsm[3200 + b * 50 + u];
                zf += zsm[b * 50 + 12 + u] + zsm[3200 + b * 50 + 12 + u];
                zg += zsm[b * 50 + 24 + u] + zsm[3200 + b * 50 + 24 + u];
                zo += zsm[b * 50 + 36 + u] + zsm[3200 + b * 50 + 36 + u];
            }
            float iv = sigf(zi), fv = sigf(zf), gv = tanh_(zg), ov = sigf(zo);
            cst[j] = fv * cst[j] + iv * gv;
            float hv = ov * tanh_(cst[j]);
            __nv_bfloat16 hi = __float2bfloat16(hv);
            __nv_bfloat16 lo = __float2bfloat16(hv - __bfloat162float(hi));
            g_hbf[dir][s % 3][0][b][u0 + u] = hi;
            g_hbf[dir][s % 3][1][b][u0 + u] = lo;
            out[((size_t)b * T_ + tt) * (2 * H_) + dir * H_ + u0 + u] = hv;
        }
        __syncthreads();
        if (tid == 0) red_rel_add1(&g_cnt[dir]);
    }
}

// =====================================================================
extern "C" void kernel_launch(void* const* d_in, const int* in_sizes, int n_in,
                              void* d_out, int out_size)
{
    const float* x  = (const float*)d_in[0];
    const float* Wf = (const float*)d_in[1];
    const float* Uf = (const float*)d_in[2];
    const float* bf = (const float*)d_in[3];
    const float* Wb = (const float*)d_in[4];
    const float* Ub = (const float*)d_in[5];
    const float* bb = (const float*)d_in[6];
    float* out = (float*)d_out;
    (void)in_sizes; (void)n_in; (void)out_size;

    cudaFuncSetAttribute(proj_mma, cudaFuncAttributeMaxDynamicSharedMemorySize, PROJ_SMEM);
    cudaFuncSetAttribute(rnn_kernel, cudaFuncAttributeMaxDynamicSharedMemorySize, RNN_SMEM);

    pack_x<<<32768, 256>>>(x);
    pack_w<<<3072, 256>>>(Wf, Wb);
    proj_mma<<<dim3(24, 512, 2), 256, PROJ_SMEM>>>(bf, bb);
    rnn_kernel<<<128, 256, RNN_SMEM>>>(Uf, Ub, out);
}